// round 12
// baseline (speedup 1.0000x reference)
#include <cuda_runtime.h>

// ----------------------------------------------------------------------------
// ControlWhile persistent kernel, R9.
// R8 post-mortem: LDS.128 neutral; warp-level cycle model shows the loop is
// LATENCY-HIDING bound at 4 warps/SMSP (fma busy == flops/duration exactly).
// R9 doubles occupancy: __launch_bounds__(512,2) -> 64-reg cap -> 2 blocks/SM
// -> 8 warps/SMSP. Prefetch dropped (TLP replaces ILP) to fit 64 regs with
// no spills (~55 live). Decide step tree-ified (chunked, fixed order).
// ----------------------------------------------------------------------------

#define CIN    3
#define COUT   16
#define HW     147456           // 384*384
#define NPIX   1179648           // 8*HW
#define NTOT   18874368.0        // NPIX*COUT elements in v
#define THRESH (3.0 * NTOT)      // mean|v| < 3  <=>  sum|v| < 3*NTOT
#define MAX_IT 64
#define MAX_BLOCKS 1024
#define TPB    512

// v, pixel-major packed: g_v[p*8 + j] = f32x2 {chan 2j, chan 2j+1} of pixel p.
__device__ __align__(16) unsigned long long g_v[(size_t)NPIX * 8];
// Per-block |v| partial sums — fully overwritten every phase (replay-safe).
__device__ double g_part[MAX_BLOCKS];
// Grid barrier: count returns to 0; gen monotonic, equality-compared (replay-safe).
__device__ unsigned int g_bar_count;
__device__ volatile unsigned int g_bar_gen;

// ---- packed f32x2 helpers (PTX-only; ptxas won't auto-fuse) ----
__device__ __forceinline__ unsigned long long ffma2(unsigned long long a,
                                                    unsigned long long b,
                                                    unsigned long long c) {
    unsigned long long d;
    asm("fma.rn.f32x2 %0, %1, %2, %3;" : "=l"(d) : "l"(a), "l"(b), "l"(c));
    return d;
}
__device__ __forceinline__ unsigned long long pack2(float lo, float hi) {
    unsigned long long d;
    asm("mov.b64 %0, {%1, %2};" : "=l"(d) : "f"(lo), "f"(hi));
    return d;
}
__device__ __forceinline__ float hadd2(unsigned long long v) {
    float lo, hi;
    asm("mov.b64 {%0, %1}, %2;" : "=f"(lo), "=f"(hi) : "l"(v));
    return lo + hi;
}

// tanh = 1 - 2/(e^{2x}+1); ~1e-7 rel err (NOT tanh.approx: ~5e-4 error is
// risky for the data-dependent trip count). Clamp at 9 exact in fp32.
__device__ __forceinline__ float tanhx(float x) {
    float xc = fminf(fmaxf(x, -9.0f), 9.0f);
    float t  = __expf(xc + xc);
    return 1.0f - __fdividef(2.0f, t + 1.0f);
}

// Software grid barrier (all blocks co-resident; verified at launch).
__device__ __forceinline__ void grid_bar() {
    __syncthreads();
    if (threadIdx.x == 0) {
        __threadfence();
        unsigned g = g_bar_gen;
        unsigned a = atomicAdd(&g_bar_count, 1u);
        if (a == gridDim.x - 1) {
            atomicExch(&g_bar_count, 0u);
            __threadfence();
            g_bar_gen = g + 1;
        } else {
            while (g_bar_gen == g) { __nanosleep(64); }
        }
    }
    __syncthreads();
}

// Block-reduce a float partial into g_part[blockIdx.x] (double).
__device__ __forceinline__ void store_block_partial(float part, double* s_wsum) {
    __syncthreads();
    float v = part;
    #pragma unroll
    for (int o = 16; o > 0; o >>= 1) v += __shfl_xor_sync(0xffffffffu, v, o);
    if ((threadIdx.x & 31) == 0) s_wsum[threadIdx.x >> 5] = (double)v;
    __syncthreads();
    if (threadIdx.x == 0) {
        double s = 0.0;
        #pragma unroll
        for (int i = 0; i < TPB / 32; i++) s += s_wsum[i];
        g_part[blockIdx.x] = s;
    }
}

__global__ void __launch_bounds__(TPB, 2)
control_while_kernel(const float* __restrict__ x,
                     const float* __restrict__ wpre, const float* __restrict__ bpre,
                     const float* __restrict__ wloop, const float* __restrict__ bloop,
                     const float* __restrict__ wsh, const float* __restrict__ bsh,
                     float* __restrict__ out)
{
    // Channel-pair-packed weights: s_w*2[o*8+j] = (w[o][2j], w[o][2j+1]).
    __shared__ __align__(16) unsigned long long s_wpre2[COUT * 2];
    __shared__ __align__(16) unsigned long long s_wsh2[COUT * 8];
    __shared__ __align__(16) unsigned long long s_wl2[COUT * 8];
    __shared__ float s_bpre[COUT], s_bsh[COUT], s_bl[COUT];
    __shared__ double s_wsum[TPB / 32];
    __shared__ double s_dec[32];
    __shared__ double s_bcast;

    {
        int t = threadIdx.x;
        if (t < COUT * 8) {
            int o = t >> 3, j = t & 7;
            s_wsh2[t] = pack2(wsh[o * COUT + 2 * j],   wsh[o * COUT + 2 * j + 1]);
            s_wl2[t]  = pack2(wloop[o * COUT + 2 * j], wloop[o * COUT + 2 * j + 1]);
        }
        if (t < COUT * 2) {
            int o = t >> 1, j = t & 1;
            s_wpre2[t] = (j == 0) ? pack2(wpre[o * CIN], wpre[o * CIN + 1])
                                  : pack2(wpre[o * CIN + 2], 0.0f);
        }
        if (t < COUT) {
            s_bpre[t] = bpre[t]; s_bsh[t] = bsh[t]; s_bl[t] = bloop[t];
        }
    }
    __syncthreads();

    const int gid    = blockIdx.x * TPB + threadIdx.x;
    const int stride = gridDim.x * TPB;

    // Batch decomposition for planar x/out. stride may exceed any sub-extent:
    // rollover is a while-loop (R3 lesson).
    const int b0i = gid / HW;
    const int i0i = gid - b0i * HW;

    // ---- phase 0: pre conv 3->16 (x planar -> v packed), sum|v| ----
    {
        float part = 0.f;
        int b = b0i, i = i0i;
        for (int q = gid; q < NPIX; q += stride) {
            const float* xp = x + (size_t)b * (CIN * HW) + i;
            unsigned long long xin0 = pack2(xp[0], xp[HW]);
            unsigned long long xin1 = pack2(xp[2 * HW], 0.0f);
            unsigned long long vo[8];
            #pragma unroll
            for (int o = 0; o < COUT; o += 2) {
                unsigned long long a0 = pack2(s_bpre[o], 0.0f);
                unsigned long long a1 = pack2(s_bpre[o + 1], 0.0f);
                a0 = ffma2(s_wpre2[2 * o],     xin0, a0);
                a0 = ffma2(s_wpre2[2 * o + 1], xin1, a0);
                a1 = ffma2(s_wpre2[2 * o + 2], xin0, a1);
                a1 = ffma2(s_wpre2[2 * o + 3], xin1, a1);
                float s0 = hadd2(a0), s1 = hadd2(a1);
                part += fabsf(s0) + fabsf(s1);
                vo[o >> 1] = pack2(s0, s1);
            }
            ulonglong2* vp2 = (ulonglong2*)(g_v + (size_t)q * 8);
            vp2[0] = make_ulonglong2(vo[0], vo[1]);
            vp2[1] = make_ulonglong2(vo[2], vo[3]);
            vp2[2] = make_ulonglong2(vo[4], vo[5]);
            vp2[3] = make_ulonglong2(vo[6], vo[7]);
            i += stride;
            while (i >= HW) { i -= HW; b++; }
        }
        store_block_partial(part, s_wsum);
    }
    grid_bar();

    // ---- data-dependent while loop, fully on-device ----
    for (int it = 0; it < MAX_IT; it++) {
        // decide: 32 threads sum fixed contiguous chunks of g_part, thread 0
        // sums the 32 partials in fixed order -> identical double everywhere.
        {
            int grid = (int)gridDim.x;
            int chunk = (grid + 31) / 32;
            if (threadIdx.x < 32) {
                double s = 0.0;
                int lo = threadIdx.x * chunk;
                int hi = lo + chunk; if (hi > grid) hi = grid;
                for (int i = lo; i < hi; i++)
                    s += ((volatile double*)g_part)[i];
                s_dec[threadIdx.x] = s;
            }
            __syncthreads();
            if (threadIdx.x == 0) {
                double s = 0.0;
                #pragma unroll
                for (int i = 0; i < 32; i++) s += s_dec[i];
                s_bcast = s;
            }
            __syncthreads();
        }
        double tot = s_bcast;
        __syncthreads();
        if (!(tot < THRESH)) break;   // NaN-safe, same as jnp semantics

        float part = 0.f;
        for (int q = gid; q < NPIX; q += stride) {
            unsigned long long vp[8];
            {
                const ulonglong2* p2 = (const ulonglong2*)(g_v + (size_t)q * 8);
                ulonglong2 t0 = p2[0], t1 = p2[1], t2 = p2[2], t3 = p2[3];
                vp[0]=t0.x; vp[1]=t0.y; vp[2]=t1.x; vp[3]=t1.y;
                vp[4]=t2.x; vp[5]=t2.y; vp[6]=t3.x; vp[7]=t3.y;
            }
            // conv w_shared + tanh -> hp (channel-pair packed)
            unsigned long long hp[8];
            #pragma unroll
            for (int o = 0; o < COUT; o += 2) {
                unsigned long long a0 = pack2(s_bsh[o], 0.0f);
                unsigned long long a1 = pack2(s_bsh[o + 1], 0.0f);
                #pragma unroll
                for (int j = 0; j < 8; j++) {
                    a0 = ffma2(s_wsh2[o * 8 + j],       vp[j], a0);
                    a1 = ffma2(s_wsh2[(o + 1) * 8 + j], vp[j], a1);
                }
                hp[o >> 1] = pack2(tanhx(hadd2(a0)), tanhx(hadd2(a1)));
            }
            // conv w_loop, *10, store packed, accumulate |.|
            ulonglong2* vs2 = (ulonglong2*)(g_v + (size_t)q * 8);
            #pragma unroll
            for (int o = 0; o < COUT; o += 4) {
                unsigned long long a0 = pack2(s_bl[o], 0.0f);
                unsigned long long a1 = pack2(s_bl[o + 1], 0.0f);
                unsigned long long a2 = pack2(s_bl[o + 2], 0.0f);
                unsigned long long a3 = pack2(s_bl[o + 3], 0.0f);
                #pragma unroll
                for (int j = 0; j < 8; j++) {
                    a0 = ffma2(s_wl2[o * 8 + j],       hp[j], a0);
                    a1 = ffma2(s_wl2[(o + 1) * 8 + j], hp[j], a1);
                    a2 = ffma2(s_wl2[(o + 2) * 8 + j], hp[j], a2);
                    a3 = ffma2(s_wl2[(o + 3) * 8 + j], hp[j], a3);
                }
                float s0 = hadd2(a0) * 10.0f, s1 = hadd2(a1) * 10.0f;
                float s2 = hadd2(a2) * 10.0f, s3 = hadd2(a3) * 10.0f;
                part += fabsf(s0) + fabsf(s1) + fabsf(s2) + fabsf(s3);
                vs2[o >> 2] = make_ulonglong2(pack2(s0, s1), pack2(s2, s3));
            }
        }
        store_block_partial(part, s_wsum);
        grid_bar();
    }

    // ---- final conv w_shared (v packed -> out planar) ----
    {
        int b = b0i, i = i0i;
        for (int q = gid; q < NPIX; q += stride) {
            const ulonglong2* p2 = (const ulonglong2*)(g_v + (size_t)q * 8);
            ulonglong2 t0 = p2[0], t1 = p2[1], t2 = p2[2], t3 = p2[3];
            unsigned long long vp[8] = {t0.x, t0.y, t1.x, t1.y,
                                        t2.x, t2.y, t3.x, t3.y};
            float* op = out + (size_t)b * (COUT * HW) + i;
            #pragma unroll
            for (int o = 0; o < COUT; o++) {
                unsigned long long a = pack2(s_bsh[o], 0.0f);
                #pragma unroll
                for (int j = 0; j < 8; j++) a = ffma2(s_wsh2[o * 8 + j], vp[j], a);
                op[(size_t)o * HW] = hadd2(a);
            }
            i += stride;
            while (i >= HW) { i -= HW; b++; }
        }
    }
}

extern "C" void kernel_launch(void* const* d_in, const int* in_sizes, int n_in,
                              void* d_out, int out_size) {
    const float* x     = (const float*)d_in[0];
    const float* wpre  = (const float*)d_in[1];
    const float* bpre  = (const float*)d_in[2];
    const float* wloop = (const float*)d_in[3];
    const float* bloop = (const float*)d_in[4];
    const float* wsh   = (const float*)d_in[5];
    const float* bsh   = (const float*)d_in[6];
    (void)in_sizes; (void)n_in; (void)out_size;

    int dev = 0;
    cudaGetDevice(&dev);
    int sms = 0;
    cudaDeviceGetAttribute(&sms, cudaDevAttrMultiProcessorCount, dev);
    if (sms < 1) sms = 148;

    // Co-residency verified, not assumed: barrier is deadlock-free iff
    // gridDim <= sms * blocksPerSM. With launch_bounds(512,2) occ should be 2.
    int occ = 0;
    cudaOccupancyMaxActiveBlocksPerMultiprocessor(&occ, control_while_kernel,
                                                  TPB, 0);
    if (occ < 1) occ = 1;
    long long want = (long long)sms * occ;
    int blocks = (want > MAX_BLOCKS) ? MAX_BLOCKS : (int)want;

    control_while_kernel<<<blocks, TPB>>>(x, wpre, bpre, wloop, bloop, wsh, bsh,
                                          (float*)d_out);
}

// round 13
// speedup vs baseline: 11.1958x; 11.1958x over previous
#include <cuda_runtime.h>

// ----------------------------------------------------------------------------
// ControlWhile persistent kernel, R10.
// R9 post-mortem: 64-reg occupancy route spills (3rd confirmation body needs
// ~90-128 regs). R5/R8 bound = LDS weight stream (256 LDS.64/pixel, L1=65%).
// R10 eliminates it: weights+biases copied into __constant__ memory via
// cudaMemcpyToSymbolAsync(D2D, graph-capturable) and read through the
// uniform-const path (LDCU floor=1, separate port, const-cache broadcast).
// Shared memory now holds only reduction scratch.
// ----------------------------------------------------------------------------

#define CIN    3
#define COUT   16
#define HW     147456           // 384*384
#define NPIX   1179648           // 8*HW
#define NTOT   18874368.0        // NPIX*COUT elements in v
#define THRESH (3.0 * NTOT)      // mean|v| < 3  <=>  sum|v| < 3*NTOT
#define MAX_IT 64
#define MAX_BLOCKS 1024
#define TPB    512

// Weights in the constant bank (uniform across the warp -> LDCU path).
__constant__ float c_wpre[COUT * CIN];
__constant__ float c_bpre[COUT];
__constant__ float c_wsh[COUT * COUT];
__constant__ float c_bsh[COUT];
__constant__ float c_wl[COUT * COUT];
__constant__ float c_bl[COUT];

// v, pixel-major packed: g_v[p*8 + j] = f32x2 {chan 2j, chan 2j+1} of pixel p.
__device__ __align__(16) unsigned long long g_v[(size_t)NPIX * 8];
// Per-block |v| partial sums — fully overwritten every phase (replay-safe).
__device__ double g_part[MAX_BLOCKS];
// Grid barrier: count returns to 0; gen monotonic, equality-compared (replay-safe).
__device__ unsigned int g_bar_count;
__device__ volatile unsigned int g_bar_gen;

// ---- packed f32x2 helpers (PTX-only; ptxas won't auto-fuse) ----
__device__ __forceinline__ unsigned long long ffma2(unsigned long long a,
                                                    unsigned long long b,
                                                    unsigned long long c) {
    unsigned long long d;
    asm("fma.rn.f32x2 %0, %1, %2, %3;" : "=l"(d) : "l"(a), "l"(b), "l"(c));
    return d;
}
__device__ __forceinline__ unsigned long long pack2(float lo, float hi) {
    unsigned long long d;
    asm("mov.b64 %0, {%1, %2};" : "=l"(d) : "f"(lo), "f"(hi));
    return d;
}
__device__ __forceinline__ float hadd2(unsigned long long v) {
    float lo, hi;
    asm("mov.b64 {%0, %1}, %2;" : "=f"(lo), "=f"(hi) : "l"(v));
    return lo + hi;
}

// tanh = 1 - 2/(e^{2x}+1); ~1e-7 rel err (NOT tanh.approx: ~5e-4 error is
// risky for the data-dependent trip count). Clamp at 9 exact in fp32.
__device__ __forceinline__ float tanhx(float x) {
    float xc = fminf(fmaxf(x, -9.0f), 9.0f);
    float t  = __expf(xc + xc);
    return 1.0f - __fdividef(2.0f, t + 1.0f);
}

// Software grid barrier (all blocks co-resident; verified at launch).
__device__ __forceinline__ void grid_bar() {
    __syncthreads();
    if (threadIdx.x == 0) {
        __threadfence();
        unsigned g = g_bar_gen;
        unsigned a = atomicAdd(&g_bar_count, 1u);
        if (a == gridDim.x - 1) {
            atomicExch(&g_bar_count, 0u);
            __threadfence();
            g_bar_gen = g + 1;
        } else {
            while (g_bar_gen == g) { __nanosleep(64); }
        }
    }
    __syncthreads();
}

// Block-reduce a float partial into g_part[blockIdx.x] (double).
__device__ __forceinline__ void store_block_partial(float part, double* s_wsum) {
    __syncthreads();
    float v = part;
    #pragma unroll
    for (int o = 16; o > 0; o >>= 1) v += __shfl_xor_sync(0xffffffffu, v, o);
    if ((threadIdx.x & 31) == 0) s_wsum[threadIdx.x >> 5] = (double)v;
    __syncthreads();
    if (threadIdx.x == 0) {
        double s = 0.0;
        #pragma unroll
        for (int i = 0; i < TPB / 32; i++) s += s_wsum[i];
        g_part[blockIdx.x] = s;
    }
}

__global__ void __launch_bounds__(TPB, 1)
control_while_kernel(const float* __restrict__ x, float* __restrict__ out)
{
    __shared__ double s_wsum[TPB / 32];
    __shared__ double s_dec[32];
    __shared__ double s_bcast;

    const int gid    = blockIdx.x * TPB + threadIdx.x;
    const int stride = gridDim.x * TPB;

    // Batch decomposition for planar x/out. stride may exceed any sub-extent:
    // rollover is a while-loop (R3 lesson).
    const int b0i = gid / HW;
    const int i0i = gid - b0i * HW;

    // ---- phase 0: pre conv 3->16 (x planar -> v packed), sum|v| ----
    {
        float part = 0.f;
        int b = b0i, i = i0i;
        for (int q = gid; q < NPIX; q += stride) {
            const float* xp = x + (size_t)b * (CIN * HW) + i;
            unsigned long long xin0 = pack2(xp[0], xp[HW]);
            unsigned long long xin1 = pack2(xp[2 * HW], 0.0f);
            unsigned long long vo[8];
            #pragma unroll
            for (int o = 0; o < COUT; o += 2) {
                unsigned long long a0 = pack2(c_bpre[o], 0.0f);
                unsigned long long a1 = pack2(c_bpre[o + 1], 0.0f);
                a0 = ffma2(pack2(c_wpre[o * CIN],     c_wpre[o * CIN + 1]), xin0, a0);
                a0 = ffma2(pack2(c_wpre[o * CIN + 2], 0.0f),                xin1, a0);
                a1 = ffma2(pack2(c_wpre[(o+1) * CIN],     c_wpre[(o+1) * CIN + 1]), xin0, a1);
                a1 = ffma2(pack2(c_wpre[(o+1) * CIN + 2], 0.0f),                    xin1, a1);
                float s0 = hadd2(a0), s1 = hadd2(a1);
                part += fabsf(s0) + fabsf(s1);
                vo[o >> 1] = pack2(s0, s1);
            }
            ulonglong2* vp2 = (ulonglong2*)(g_v + (size_t)q * 8);
            vp2[0] = make_ulonglong2(vo[0], vo[1]);
            vp2[1] = make_ulonglong2(vo[2], vo[3]);
            vp2[2] = make_ulonglong2(vo[4], vo[5]);
            vp2[3] = make_ulonglong2(vo[6], vo[7]);
            i += stride;
            while (i >= HW) { i -= HW; b++; }
        }
        store_block_partial(part, s_wsum);
    }
    grid_bar();

    // ---- data-dependent while loop, fully on-device ----
    for (int it = 0; it < MAX_IT; it++) {
        // decide: 32 threads sum fixed contiguous chunks of g_part, thread 0
        // sums the 32 partials in fixed order -> identical double everywhere.
        {
            int grid = (int)gridDim.x;
            int chunk = (grid + 31) / 32;
            if (threadIdx.x < 32) {
                double s = 0.0;
                int lo = threadIdx.x * chunk;
                int hi = lo + chunk; if (hi > grid) hi = grid;
                for (int i = lo; i < hi; i++)
                    s += ((volatile double*)g_part)[i];
                s_dec[threadIdx.x] = s;
            }
            __syncthreads();
            if (threadIdx.x == 0) {
                double s = 0.0;
                #pragma unroll
                for (int i = 0; i < 32; i++) s += s_dec[i];
                s_bcast = s;
            }
            __syncthreads();
        }
        double tot = s_bcast;
        __syncthreads();
        if (!(tot < THRESH)) break;   // NaN-safe, same as jnp semantics

        float part = 0.f;
        for (int q = gid; q < NPIX; q += stride) {
            unsigned long long vp[8];
            {
                const ulonglong2* p2 = (const ulonglong2*)(g_v + (size_t)q * 8);
                ulonglong2 t0 = p2[0], t1 = p2[1], t2 = p2[2], t3 = p2[3];
                vp[0]=t0.x; vp[1]=t0.y; vp[2]=t1.x; vp[3]=t1.y;
                vp[4]=t2.x; vp[5]=t2.y; vp[6]=t3.x; vp[7]=t3.y;
            }
            // conv w_shared + tanh -> hp (channel-pair packed); weights via LDCU
            unsigned long long hp[8];
            #pragma unroll
            for (int o = 0; o < COUT; o += 2) {
                unsigned long long a0 = pack2(c_bsh[o], 0.0f);
                unsigned long long a1 = pack2(c_bsh[o + 1], 0.0f);
                #pragma unroll
                for (int j = 0; j < 8; j++) {
                    a0 = ffma2(pack2(c_wsh[o * COUT + 2*j],     c_wsh[o * COUT + 2*j + 1]),     vp[j], a0);
                    a1 = ffma2(pack2(c_wsh[(o+1) * COUT + 2*j], c_wsh[(o+1) * COUT + 2*j + 1]), vp[j], a1);
                }
                hp[o >> 1] = pack2(tanhx(hadd2(a0)), tanhx(hadd2(a1)));
            }
            // conv w_loop, *10, store packed, accumulate |.|
            ulonglong2* vs2 = (ulonglong2*)(g_v + (size_t)q * 8);
            #pragma unroll
            for (int o = 0; o < COUT; o += 4) {
                unsigned long long a0 = pack2(c_bl[o], 0.0f);
                unsigned long long a1 = pack2(c_bl[o + 1], 0.0f);
                unsigned long long a2 = pack2(c_bl[o + 2], 0.0f);
                unsigned long long a3 = pack2(c_bl[o + 3], 0.0f);
                #pragma unroll
                for (int j = 0; j < 8; j++) {
                    a0 = ffma2(pack2(c_wl[o * COUT + 2*j],       c_wl[o * COUT + 2*j + 1]),       hp[j], a0);
                    a1 = ffma2(pack2(c_wl[(o+1) * COUT + 2*j],   c_wl[(o+1) * COUT + 2*j + 1]),   hp[j], a1);
                    a2 = ffma2(pack2(c_wl[(o+2) * COUT + 2*j],   c_wl[(o+2) * COUT + 2*j + 1]),   hp[j], a2);
                    a3 = ffma2(pack2(c_wl[(o+3) * COUT + 2*j],   c_wl[(o+3) * COUT + 2*j + 1]),   hp[j], a3);
                }
                float s0 = hadd2(a0) * 10.0f, s1 = hadd2(a1) * 10.0f;
                float s2 = hadd2(a2) * 10.0f, s3 = hadd2(a3) * 10.0f;
                part += fabsf(s0) + fabsf(s1) + fabsf(s2) + fabsf(s3);
                vs2[o >> 2] = make_ulonglong2(pack2(s0, s1), pack2(s2, s3));
            }
        }
        store_block_partial(part, s_wsum);
        grid_bar();
    }

    // ---- final conv w_shared (v packed -> out planar) ----
    {
        int b = b0i, i = i0i;
        for (int q = gid; q < NPIX; q += stride) {
            const ulonglong2* p2 = (const ulonglong2*)(g_v + (size_t)q * 8);
            ulonglong2 t0 = p2[0], t1 = p2[1], t2 = p2[2], t3 = p2[3];
            unsigned long long vp[8] = {t0.x, t0.y, t1.x, t1.y,
                                        t2.x, t2.y, t3.x, t3.y};
            float* op = out + (size_t)b * (COUT * HW) + i;
            #pragma unroll
            for (int o = 0; o < COUT; o++) {
                unsigned long long a = pack2(c_bsh[o], 0.0f);
                #pragma unroll
                for (int j = 0; j < 8; j++)
                    a = ffma2(pack2(c_wsh[o * COUT + 2*j], c_wsh[o * COUT + 2*j + 1]),
                              vp[j], a);
                op[(size_t)o * HW] = hadd2(a);
            }
            i += stride;
            while (i >= HW) { i -= HW; b++; }
        }
    }
}

extern "C" void kernel_launch(void* const* d_in, const int* in_sizes, int n_in,
                              void* d_out, int out_size) {
    const float* x     = (const float*)d_in[0];
    const float* wpre  = (const float*)d_in[1];
    const float* bpre  = (const float*)d_in[2];
    const float* wloop = (const float*)d_in[3];
    const float* bloop = (const float*)d_in[4];
    const float* wsh   = (const float*)d_in[5];
    const float* bsh   = (const float*)d_in[6];
    (void)in_sizes; (void)n_in; (void)out_size;

    // Device-to-device async copies into the constant bank: graph-capturable
    // (no alloc, no sync). These become memcpy nodes preceding the kernel node.
    cudaMemcpyToSymbolAsync(c_wpre, wpre, COUT * CIN * sizeof(float), 0,
                            cudaMemcpyDeviceToDevice);
    cudaMemcpyToSymbolAsync(c_bpre, bpre, COUT * sizeof(float), 0,
                            cudaMemcpyDeviceToDevice);
    cudaMemcpyToSymbolAsync(c_wsh,  wsh,  COUT * COUT * sizeof(float), 0,
                            cudaMemcpyDeviceToDevice);
    cudaMemcpyToSymbolAsync(c_bsh,  bsh,  COUT * sizeof(float), 0,
                            cudaMemcpyDeviceToDevice);
    cudaMemcpyToSymbolAsync(c_wl,   wloop, COUT * COUT * sizeof(float), 0,
                            cudaMemcpyDeviceToDevice);
    cudaMemcpyToSymbolAsync(c_bl,   bloop, COUT * sizeof(float), 0,
                            cudaMemcpyDeviceToDevice);

    int dev = 0;
    cudaGetDevice(&dev);
    int sms = 0;
    cudaDeviceGetAttribute(&sms, cudaDevAttrMultiProcessorCount, dev);
    if (sms < 1) sms = 148;

    // Co-residency verified, not assumed: barrier is deadlock-free iff
    // gridDim <= sms * blocksPerSM.
    int occ = 0;
    cudaOccupancyMaxActiveBlocksPerMultiprocessor(&occ, control_while_kernel,
                                                  TPB, 0);
    if (occ < 1) occ = 1;
    long long want = (long long)sms * occ;
    int blocks = (want > MAX_BLOCKS) ? MAX_BLOCKS : (int)want;

    control_while_kernel<<<blocks, TPB>>>(x, (float*)d_out);
}

// round 14
// speedup vs baseline: 12.7622x; 1.1399x over previous
#include <cuda_runtime.h>

// ----------------------------------------------------------------------------
// ControlWhile persistent kernel, R11.
// R10 (217us) is issue/instruction-bound: ~750 instrs/pixel, tanh = 128 ops
// incl 32 MUFU (rt=8 -> half the fma-pipe pressure). R11:
//  (1) tanh.approx.f32 (1 MUFU, ~5e-4 rel err; trip-count margin analysis in
//      round notes, expected final rel_err ~1e-4 < 1e-3 gate)
//  (2) weights pre-packed into 64-bit constants by a prep kernel (guaranteed
//      one LDC.64 per FFMA2) with the *10 folded into w_loop/b_loop.
// ----------------------------------------------------------------------------

#define CIN    3
#define COUT   16
#define HW     147456            // 384*384
#define NPIX   1179648           // 8*HW
#define NTOT   18874368.0        // NPIX*COUT elements in v
#define THRESH (3.0 * NTOT)      // mean|v| < 3  <=>  sum|v| < 3*NTOT
#define MAX_IT 64
#define MAX_BLOCKS 1024
#define TPB    512

typedef unsigned long long u64;

// Pre-packed weights in the constant bank (one 64-bit const load per FFMA2).
__constant__ u64 k_wpre2[COUT * 2];   // [o*2+{0,1}] = (w0,w1),(w2,0)
__constant__ u64 k_bpre2[COUT];       // (b,0)
__constant__ u64 k_wsh2[COUT * 8];    // [o*8+j] = (w[o][2j], w[o][2j+1])
__constant__ u64 k_bsh2[COUT];        // (b,0)
__constant__ u64 k_wl2[COUT * 8];     // prescaled by 10
__constant__ u64 k_bl2[COUT];         // prescaled by 10, (b,0)

// Staging for the prep kernel (cannot write __constant__ from device code).
__device__ u64 g_pk[COUT * 2 + COUT + COUT * 8 + COUT + COUT * 8 + COUT];

// v, pixel-major packed: g_v[p*8 + j] = f32x2 {chan 2j, chan 2j+1} of pixel p.
__device__ __align__(16) u64 g_v[(size_t)NPIX * 8];
// Per-block |v| partial sums — fully overwritten every phase (replay-safe).
__device__ double g_part[MAX_BLOCKS];
// Grid barrier: count returns to 0; gen monotonic, equality-compared (replay-safe).
__device__ unsigned int g_bar_count;
__device__ volatile unsigned int g_bar_gen;

// ---- packed f32x2 helpers (PTX-only; ptxas won't auto-fuse) ----
__device__ __forceinline__ u64 ffma2(u64 a, u64 b, u64 c) {
    u64 d;
    asm("fma.rn.f32x2 %0, %1, %2, %3;" : "=l"(d) : "l"(a), "l"(b), "l"(c));
    return d;
}
__device__ __forceinline__ u64 pack2(float lo, float hi) {
    u64 d;
    asm("mov.b64 %0, {%1, %2};" : "=l"(d) : "f"(lo), "f"(hi));
    return d;
}
__device__ __forceinline__ float hadd2(u64 v) {
    float lo, hi;
    asm("mov.b64 {%0, %1}, %2;" : "=f"(lo), "=f"(hi) : "l"(v));
    return lo + hi;
}

// HW tanh approximation: 1 MUFU op. Max rel err ~5e-4 — margin analysis vs the
// data-dependent trip count and the 1e-3 output gate in the round notes.
__device__ __forceinline__ float tanha(float x) {
    float y;
    asm("tanh.approx.f32 %0, %1;" : "=f"(y) : "f"(x));
    return y;
}

// Software grid barrier (all blocks co-resident; verified at launch).
__device__ __forceinline__ void grid_bar() {
    __syncthreads();
    if (threadIdx.x == 0) {
        __threadfence();
        unsigned g = g_bar_gen;
        unsigned a = atomicAdd(&g_bar_count, 1u);
        if (a == gridDim.x - 1) {
            atomicExch(&g_bar_count, 0u);
            __threadfence();
            g_bar_gen = g + 1;
        } else {
            while (g_bar_gen == g) { __nanosleep(64); }
        }
    }
    __syncthreads();
}

// Block-reduce a float partial into g_part[blockIdx.x] (double).
__device__ __forceinline__ void store_block_partial(float part, double* s_wsum) {
    __syncthreads();
    float v = part;
    #pragma unroll
    for (int o = 16; o > 0; o >>= 1) v += __shfl_xor_sync(0xffffffffu, v, o);
    if ((threadIdx.x & 31) == 0) s_wsum[threadIdx.x >> 5] = (double)v;
    __syncthreads();
    if (threadIdx.x == 0) {
        double s = 0.0;
        #pragma unroll
        for (int i = 0; i < TPB / 32; i++) s += s_wsum[i];
        g_part[blockIdx.x] = s;
    }
}

// ---- prep kernel: pack/prescale weights into staging (then D2D -> constant) --
__global__ void prep_kernel(const float* __restrict__ wpre,
                            const float* __restrict__ bpre,
                            const float* __restrict__ wloop,
                            const float* __restrict__ bloop,
                            const float* __restrict__ wsh,
                            const float* __restrict__ bsh)
{
    int t = threadIdx.x;
    u64* pk_wpre = g_pk;
    u64* pk_bpre = pk_wpre + COUT * 2;
    u64* pk_wsh  = pk_bpre + COUT;
    u64* pk_bsh  = pk_wsh + COUT * 8;
    u64* pk_wl   = pk_bsh + COUT;
    u64* pk_bl   = pk_wl + COUT * 8;

    if (t < COUT * 8) {
        int o = t >> 3, j = t & 7;
        pk_wsh[t] = pack2(wsh[o * COUT + 2 * j], wsh[o * COUT + 2 * j + 1]);
        pk_wl[t]  = pack2(10.0f * wloop[o * COUT + 2 * j],
                          10.0f * wloop[o * COUT + 2 * j + 1]);
    }
    if (t < COUT * 2) {
        int o = t >> 1, j = t & 1;
        pk_wpre[t] = (j == 0) ? pack2(wpre[o * CIN], wpre[o * CIN + 1])
                              : pack2(wpre[o * CIN + 2], 0.0f);
    }
    if (t < COUT) {
        pk_bpre[t] = pack2(bpre[t], 0.0f);
        pk_bsh[t]  = pack2(bsh[t], 0.0f);
        pk_bl[t]   = pack2(10.0f * bloop[t], 0.0f);
    }
}

__global__ void __launch_bounds__(TPB, 1)
control_while_kernel(const float* __restrict__ x, float* __restrict__ out)
{
    __shared__ double s_wsum[TPB / 32];
    __shared__ double s_dec[32];
    __shared__ double s_bcast;

    const int gid    = blockIdx.x * TPB + threadIdx.x;
    const int stride = gridDim.x * TPB;

    // Batch decomposition for planar x/out. stride may exceed any sub-extent:
    // rollover is a while-loop (R3 lesson).
    const int b0i = gid / HW;
    const int i0i = gid - b0i * HW;

    // ---- phase 0: pre conv 3->16 (x planar -> v packed), sum|v| ----
    {
        float part = 0.f;
        int b = b0i, i = i0i;
        for (int q = gid; q < NPIX; q += stride) {
            const float* xp = x + (size_t)b * (CIN * HW) + i;
            u64 xin0 = pack2(xp[0], xp[HW]);
            u64 xin1 = pack2(xp[2 * HW], 0.0f);
            u64 vo[8];
            #pragma unroll
            for (int o = 0; o < COUT; o += 2) {
                u64 a0 = k_bpre2[o];
                u64 a1 = k_bpre2[o + 1];
                a0 = ffma2(k_wpre2[2 * o],     xin0, a0);
                a0 = ffma2(k_wpre2[2 * o + 1], xin1, a0);
                a1 = ffma2(k_wpre2[2 * o + 2], xin0, a1);
                a1 = ffma2(k_wpre2[2 * o + 3], xin1, a1);
                float s0 = hadd2(a0), s1 = hadd2(a1);
                part += fabsf(s0) + fabsf(s1);
                vo[o >> 1] = pack2(s0, s1);
            }
            ulonglong2* vp2 = (ulonglong2*)(g_v + (size_t)q * 8);
            vp2[0] = make_ulonglong2(vo[0], vo[1]);
            vp2[1] = make_ulonglong2(vo[2], vo[3]);
            vp2[2] = make_ulonglong2(vo[4], vo[5]);
            vp2[3] = make_ulonglong2(vo[6], vo[7]);
            i += stride;
            while (i >= HW) { i -= HW; b++; }
        }
        store_block_partial(part, s_wsum);
    }
    grid_bar();

    // ---- data-dependent while loop, fully on-device ----
    for (int it = 0; it < MAX_IT; it++) {
        // decide: 32 threads sum fixed contiguous chunks of g_part, thread 0
        // sums the 32 partials in fixed order -> identical double everywhere.
        {
            int grid = (int)gridDim.x;
            int chunk = (grid + 31) / 32;
            if (threadIdx.x < 32) {
                double s = 0.0;
                int lo = threadIdx.x * chunk;
                int hi = lo + chunk; if (hi > grid) hi = grid;
                for (int i = lo; i < hi; i++)
                    s += ((volatile double*)g_part)[i];
                s_dec[threadIdx.x] = s;
            }
            __syncthreads();
            if (threadIdx.x == 0) {
                double s = 0.0;
                #pragma unroll
                for (int i = 0; i < 32; i++) s += s_dec[i];
                s_bcast = s;
            }
            __syncthreads();
        }
        double tot = s_bcast;
        __syncthreads();
        if (!(tot < THRESH)) break;   // NaN-safe, same as jnp semantics

        float part = 0.f;
        for (int q = gid; q < NPIX; q += stride) {
            u64 vp[8];
            {
                const ulonglong2* p2 = (const ulonglong2*)(g_v + (size_t)q * 8);
                ulonglong2 t0 = p2[0], t1 = p2[1], t2 = p2[2], t3 = p2[3];
                vp[0]=t0.x; vp[1]=t0.y; vp[2]=t1.x; vp[3]=t1.y;
                vp[4]=t2.x; vp[5]=t2.y; vp[6]=t3.x; vp[7]=t3.y;
            }
            // conv w_shared + tanh.approx -> hp (channel-pair packed)
            u64 hp[8];
            #pragma unroll
            for (int o = 0; o < COUT; o += 2) {
                u64 a0 = k_bsh2[o];
                u64 a1 = k_bsh2[o + 1];
                #pragma unroll
                for (int j = 0; j < 8; j++) {
                    a0 = ffma2(k_wsh2[o * 8 + j],       vp[j], a0);
                    a1 = ffma2(k_wsh2[(o + 1) * 8 + j], vp[j], a1);
                }
                hp[o >> 1] = pack2(tanha(hadd2(a0)), tanha(hadd2(a1)));
            }
            // conv w_loop (prescaled by 10), store packed, accumulate |.|
            ulonglong2* vs2 = (ulonglong2*)(g_v + (size_t)q * 8);
            #pragma unroll
            for (int o = 0; o < COUT; o += 4) {
                u64 a0 = k_bl2[o];
                u64 a1 = k_bl2[o + 1];
                u64 a2 = k_bl2[o + 2];
                u64 a3 = k_bl2[o + 3];
                #pragma unroll
                for (int j = 0; j < 8; j++) {
                    a0 = ffma2(k_wl2[o * 8 + j],       hp[j], a0);
                    a1 = ffma2(k_wl2[(o + 1) * 8 + j], hp[j], a1);
                    a2 = ffma2(k_wl2[(o + 2) * 8 + j], hp[j], a2);
                    a3 = ffma2(k_wl2[(o + 3) * 8 + j], hp[j], a3);
                }
                float s0 = hadd2(a0), s1 = hadd2(a1);
                float s2 = hadd2(a2), s3 = hadd2(a3);
                part += fabsf(s0) + fabsf(s1) + fabsf(s2) + fabsf(s3);
                vs2[o >> 2] = make_ulonglong2(pack2(s0, s1), pack2(s2, s3));
            }
        }
        store_block_partial(part, s_wsum);
        grid_bar();
    }

    // ---- final conv w_shared (v packed -> out planar) ----
    {
        int b = b0i, i = i0i;
        for (int q = gid; q < NPIX; q += stride) {
            const ulonglong2* p2 = (const ulonglong2*)(g_v + (size_t)q * 8);
            ulonglong2 t0 = p2[0], t1 = p2[1], t2 = p2[2], t3 = p2[3];
            u64 vp[8] = {t0.x, t0.y, t1.x, t1.y, t2.x, t2.y, t3.x, t3.y};
            float* op = out + (size_t)b * (COUT * HW) + i;
            #pragma unroll
            for (int o = 0; o < COUT; o++) {
                u64 a = k_bsh2[o];
                #pragma unroll
                for (int j = 0; j < 8; j++)
                    a = ffma2(k_wsh2[o * 8 + j], vp[j], a);
                op[(size_t)o * HW] = hadd2(a);
            }
            i += stride;
            while (i >= HW) { i -= HW; b++; }
        }
    }
}

extern "C" void kernel_launch(void* const* d_in, const int* in_sizes, int n_in,
                              void* d_out, int out_size) {
    const float* x     = (const float*)d_in[0];
    const float* wpre  = (const float*)d_in[1];
    const float* bpre  = (const float*)d_in[2];
    const float* wloop = (const float*)d_in[3];
    const float* bloop = (const float*)d_in[4];
    const float* wsh   = (const float*)d_in[5];
    const float* bsh   = (const float*)d_in[6];
    (void)in_sizes; (void)n_in; (void)out_size;

    // 1) pack/prescale weights into staging (device kernel, capture-safe)
    prep_kernel<<<1, 256>>>(wpre, bpre, wloop, bloop, wsh, bsh);

    // 2) D2D async copies staging -> constant bank (graph-capturable)
    void* pk_addr = nullptr;
    cudaGetSymbolAddress(&pk_addr, g_pk);
    const u64* pk = (const u64*)pk_addr;
    size_t off = 0;
    cudaMemcpyToSymbolAsync(k_wpre2, pk + off, COUT * 2 * sizeof(u64), 0,
                            cudaMemcpyDeviceToDevice); off += COUT * 2;
    cudaMemcpyToSymbolAsync(k_bpre2, pk + off, COUT * sizeof(u64), 0,
                            cudaMemcpyDeviceToDevice); off += COUT;
    cudaMemcpyToSymbolAsync(k_wsh2,  pk + off, COUT * 8 * sizeof(u64), 0,
                            cudaMemcpyDeviceToDevice); off += COUT * 8;
    cudaMemcpyToSymbolAsync(k_bsh2,  pk + off, COUT * sizeof(u64), 0,
                            cudaMemcpyDeviceToDevice); off += COUT;
    cudaMemcpyToSymbolAsync(k_wl2,   pk + off, COUT * 8 * sizeof(u64), 0,
                            cudaMemcpyDeviceToDevice); off += COUT * 8;
    cudaMemcpyToSymbolAsync(k_bl2,   pk + off, COUT * sizeof(u64), 0,
                            cudaMemcpyDeviceToDevice);

    int dev = 0;
    cudaGetDevice(&dev);
    int sms = 0;
    cudaDeviceGetAttribute(&sms, cudaDevAttrMultiProcessorCount, dev);
    if (sms < 1) sms = 148;

    // Co-residency verified, not assumed: barrier is deadlock-free iff
    // gridDim <= sms * blocksPerSM.
    int occ = 0;
    cudaOccupancyMaxActiveBlocksPerMultiprocessor(&occ, control_while_kernel,
                                                  TPB, 0);
    if (occ < 1) occ = 1;
    long long want = (long long)sms * occ;
    int blocks = (want > MAX_BLOCKS) ? MAX_BLOCKS : (int)want;

    control_while_kernel<<<blocks, TPB>>>(x, (float*)d_out);
}